// round 10
// baseline (speedup 1.0000x reference)
#include <cuda_runtime.h>
#include <math.h>

#define C_IN   128
#define NMAX   50000
#define EMAX   800000
#define SLAB   (NMAX * C_IN)
#define MAXK   20
#define NFILT  4
#define NBLK   148

__device__ float g_Y[(long long)MAXK * SLAB];   // Tx_0..Tx_19
__device__ float g_O[(long long)NFILT * SLAB];  // filter outputs
__device__ int2  g_csr[EMAX];                   // {src, float_bits(w)} grouped by dst
__device__ int   g_rowptr[NMAX + 1];
__device__ int   g_deg[NMAX];
__device__ int   g_indeg[NMAX];
__device__ int   g_fill[NMAX];
__device__ float g_dinv[NMAX];
__device__ int   g_is64;
__device__ unsigned g_bar;
__device__ int   g_bsum[NBLK];

// ----------------------------------------------------------- fused init ----

__global__ void init_kernel(const float4* __restrict__ x, int n4, int n,
                            const int* __restrict__ ei32, int E2) {
    int stride = gridDim.x * blockDim.x;
    int g = blockIdx.x * blockDim.x + threadIdx.x;
    float4* dst = (float4*)g_Y;
    for (int i = g; i < n4; i += stride) dst[i] = x[i];
    for (int i = g; i < n; i += stride) { g_deg[i] = 0; g_indeg[i] = 0; g_fill[i] = 0; }
    if (g == 0) g_bar = 0;
    if (blockIdx.x == 0) {
        __shared__ int any_nonzero;
        if (threadIdx.x == 0) any_nonzero = 0;
        __syncthreads();
        for (int i = threadIdx.x; i < 4096; i += blockDim.x) {
            int idx = 2 * i + 1;
            if (idx < E2 && ei32[idx] != 0) any_nonzero = 1;
        }
        __syncthreads();
        if (threadIdx.x == 0) g_is64 = any_nonzero ? 0 : 1;
    }
}

__device__ __forceinline__ int load_idx(const void* ei, long long pos) {
    if (g_is64) return (int)((const long long*)ei)[pos];
    return ((const int*)ei)[pos];
}

// -------------------------------------------------- fused graph build ------

__device__ __forceinline__ void grid_sync(int phase) {
    __syncthreads();
    if (threadIdx.x == 0) {
        __threadfence();
        atomicAdd(&g_bar, 1u);
        unsigned target = (unsigned)phase * (unsigned)gridDim.x;
        while (atomicAdd(&g_bar, 0u) < target) { }
    }
    __syncthreads();
}

__global__ void __launch_bounds__(256) build_kernel(const void* __restrict__ ei,
                                                    int E, int n) {
    const int tid = threadIdx.x, bid = blockIdx.x, nb = gridDim.x;
    const int lane = tid & 31, wid = tid >> 5;
    const int gsz = nb * 256;
    const int g = bid * 256 + tid;

    for (int e = g; e < E; e += gsz) {
        int s = load_idx(ei, e);
        int d = load_idx(ei, (long long)E + e);
        if ((unsigned)s < (unsigned)n) atomicAdd(&g_deg[s], 1);
        if ((unsigned)d < (unsigned)n) atomicAdd(&g_indeg[d], 1);
    }
    grid_sync(1);

    for (int i = g; i < n; i += gsz) {
        int d = g_deg[i];
        g_dinv[i] = (d > 0) ? rsqrtf((float)d) : 0.0f;
    }
    const int chunk = (n + nb - 1) / nb;
    const int c0 = bid * chunk;
    const int c1 = min(c0 + chunk, n);
    int local = 0;
    for (int i = c0 + tid; i < c1; i += 256) local += g_indeg[i];
    __shared__ int red[32];
    #pragma unroll
    for (int o = 16; o > 0; o >>= 1) local += __shfl_xor_sync(0xffffffffu, local, o);
    if (lane == 0) red[wid] = local;
    __syncthreads();
    if (wid == 0) {
        int v = (lane < 8) ? red[lane] : 0;
        #pragma unroll
        for (int o = 4; o > 0; o >>= 1) v += __shfl_xor_sync(0xffffffffu, v, o);
        if (lane == 0) g_bsum[bid] = v;
    }
    grid_sync(2);

    if (bid == 0 && wid == 0) {
        int run = 0;
        for (int s0 = 0; s0 < nb; s0 += 32) {
            int i = s0 + lane;
            int v = (i < nb) ? g_bsum[i] : 0;
            int x = v;
            #pragma unroll
            for (int d = 1; d < 32; d <<= 1) {
                int y = __shfl_up_sync(0xffffffffu, x, d);
                if (lane >= d) x += y;
            }
            if (i < nb) g_bsum[i] = run + x - v;
            run += __shfl_sync(0xffffffffu, x, 31);
        }
    }
    grid_sync(3);

    {
        int carry = g_bsum[bid];
        if (bid == 0 && tid == 0) g_rowptr[0] = 0;
        __shared__ int wsum[8];
        for (int s0 = c0; s0 < c1; s0 += 256) {
            int i = s0 + tid;
            int v = (i < c1) ? g_indeg[i] : 0;
            int x = v;
            #pragma unroll
            for (int d = 1; d < 32; d <<= 1) {
                int y = __shfl_up_sync(0xffffffffu, x, d);
                if (lane >= d) x += y;
            }
            if (lane == 31) wsum[wid] = x;
            __syncthreads();
            if (wid == 0 && lane < 8) {
                int s = wsum[lane];
                #pragma unroll
                for (int d = 1; d < 8; d <<= 1) {
                    int y = __shfl_up_sync(0xffu, s, d);
                    if (lane >= d) s += y;
                }
                wsum[lane] = s;
            }
            __syncthreads();
            int pre = (wid > 0) ? wsum[wid - 1] : 0;
            if (i < c1) g_rowptr[i + 1] = carry + pre + x;
            carry += wsum[7];
            __syncthreads();
        }
    }
    grid_sync(4);

    for (int e = g; e < E; e += gsz) {
        int s = load_idx(ei, e);
        int d = load_idx(ei, (long long)E + e);
        if ((unsigned)s >= (unsigned)n || (unsigned)d >= (unsigned)n) continue;
        float w = -g_dinv[s] * g_dinv[d] - 1.0f;   // self-loops -> exactly 0, omitted
        int pos = g_rowptr[d] + atomicAdd(&g_fill[d], 1);
        if (pos < EMAX) g_csr[pos] = make_int2(s, __float_as_int(w));
    }
}

// ---------------------------------------------------------- propagation ----
// warp-per-node gather SpMM, fully software-pipelined:
//   indices prefetched 2 iterations ahead, values 1 iteration ahead.
// Steady state issues next-iter loads before consuming current values, so
// the loop-carried chain is FMA-only; gather latency spans a full iteration.
// All prefetch indices clamp to e-1 (csr entries always hold valid src), and
// clamped entries are never consumed (trip-count-guarded).

__device__ __forceinline__ void fma4(float4& a, float w, const float4 v) {
    a.x = fmaf(w, v.x, a.x); a.y = fmaf(w, v.y, a.y);
    a.z = fmaf(w, v.z, a.z); a.w = fmaf(w, v.w, a.w);
}

__global__ void __launch_bounds__(256, 5) prop_kernel(int outSlab, int inSlab,
                                                      int prevSlab, int first, int n) {
    int gw = (blockIdx.x * blockDim.x + threadIdx.x) >> 5;
    if (gw >= n) return;
    int lane = threadIdx.x & 31;
    const float4* __restrict__ Yin = (const float4*)(g_Y + (long long)inSlab * SLAB);
    int s = g_rowptr[gw], e = g_rowptr[gw + 1];
    float4 a0 = make_float4(0.f, 0.f, 0.f, 0.f);
    float4 a1 = make_float4(0.f, 0.f, 0.f, 0.f);

    if (s < e) {
        int last = e - 1;
        int i = s;
        // preload indices for iter0 & iter1, values for iter0
        int2 p0 = g_csr[i];
        int2 p1 = g_csr[min(i + 1, last)];
        int2 p2 = g_csr[min(i + 2, last)];
        int2 p3 = g_csr[min(i + 3, last)];
        float4 v0 = Yin[p0.x * 32 + lane];
        float4 v1 = Yin[p1.x * 32 + lane];
        for (; i + 2 <= e; i += 2) {
            // prefetch indices 2 iters out
            int2 q0 = g_csr[min(i + 4, last)];
            int2 q1 = g_csr[min(i + 5, last)];
            // load values 1 iter out
            float4 w0 = Yin[p2.x * 32 + lane];
            float4 w1 = Yin[p3.x * 32 + lane];
            // consume current (loaded a full iteration ago)
            fma4(a0, __int_as_float(p0.y), v0);
            fma4(a1, __int_as_float(p1.y), v1);
            p0 = p2; p1 = p3; p2 = q0; p3 = q1;
            v0 = w0; v1 = w1;
        }
        if (i < e) {   // exactly one edge left; invariant: p0 == csr[i], v0 loaded
            fma4(a0, __int_as_float(p0.y), v0);
        }
    }

    float4 r = make_float4(a0.x + a1.x, a0.y + a1.y, a0.z + a1.z, a0.w + a1.w);
    if (!first) {
        const float4* Yp = (const float4*)(g_Y + (long long)prevSlab * SLAB);
        float4 pv = Yp[gw * 32 + lane];
        r.x = 2.f * r.x - pv.x; r.y = 2.f * r.y - pv.y;
        r.z = 2.f * r.z - pv.z; r.w = 2.f * r.w - pv.w;
    }
    ((float4*)(g_Y + (long long)outSlab * SLAB))[gw * 32 + lane] = r;
}

// ------------------------------------------------------------ tf32 GEMM ----

#define LDAg 68
#define LDBg 264
#define A_STAGE (128 * LDAg)
#define B_STAGE (64 * LDBg)
#define GEMM_SMEM ((2 * A_STAGE + 2 * B_STAGE) * 4)

__device__ __forceinline__ void cp16(unsigned dst, const void* src, int srcsz) {
    asm volatile("cp.async.cg.shared.global [%0], [%1], 16, %2;\n"
                 :: "r"(dst), "l"(src), "r"(srcsz));
}

__global__ void __launch_bounds__(512, 1)
gemm_kernel(const float* __restrict__ Wg, const float* __restrict__ bias, int n) {
    extern __shared__ unsigned smem_u[];

    const int z = blockIdx.z;
    const int KfA  = z ? 15 : 5;
    const int KfB  = z ? 20 : 10;
    const int offA = z ? 15 : 0;
    const int offB = z ? 30 : 5;
    const int nChunk = KfB * 2;

    const int m0  = blockIdx.x * 128;
    const int tid = threadIdx.x;
    const int warp = tid >> 5, lane = tid & 31;
    const int wm = warp & 3, wn = warp >> 2;
    const int myK = (wn < 2) ? KfA : KfB;

    const unsigned smemBase = (unsigned)__cvta_generic_to_shared(smem_u);
    const unsigned bsBase   = smemBase + 2u * A_STAGE * 4u;

    float acc[2][8][4];
    #pragma unroll
    for (int a = 0; a < 2; a++)
        #pragma unroll
        for (int b = 0; b < 8; b++)
            #pragma unroll
            for (int c = 0; c < 4; c++) acc[a][b][c] = 0.f;

    auto load_chunk = [&](int c) {
        int stage = c & 1;
        int slab  = c >> 1;
        int kc0   = (c & 1) * 64;
        const float* A = g_Y + (long long)slab * SLAB;
        unsigned as = smemBase + (unsigned)(stage * A_STAGE) * 4u;
        #pragma unroll
        for (int j = 0; j < 4; j++) {
            int i = tid + j * 512;
            int r = i >> 4, c16 = i & 15;
            int row = m0 + r;
            const float* src = A + (long long)row * 128 + kc0 + c16 * 4;
            cp16(as + (unsigned)(r * LDAg + c16 * 4) * 4u, src, (row < n) ? 16 : 0);
        }
        unsigned bs = bsBase + (unsigned)(stage * B_STAGE) * 4u;
        #pragma unroll
        for (int j = 0; j < 8; j++) {
            int i = tid + j * 512;
            int half = i >> 11, ii = i & 2047;
            int r = ii >> 5, c16 = ii & 31;
            int Kh   = half ? KfB : KfA;
            int offh = half ? offB : offA;
            if (slab < Kh) {
                const float* src = Wg + (long long)(offh + slab) * 16384
                                      + (kc0 + r) * 128 + c16 * 4;
                cp16(bs + (unsigned)(r * LDBg + half * 128 + c16 * 4) * 4u, src, 16);
            }
        }
        asm volatile("cp.async.commit_group;\n");
    };

    load_chunk(0);
    for (int c = 0; c < nChunk; c++) {
        if (c + 1 < nChunk) load_chunk(c + 1);
        else asm volatile("cp.async.commit_group;\n");
        asm volatile("cp.async.wait_group 1;\n");
        __syncthreads();

        int slab = c >> 1;
        if (slab < myK) {
            const unsigned* As = smem_u + (c & 1) * A_STAGE;
            const unsigned* Bs = smem_u + 2 * A_STAGE + (c & 1) * B_STAGE;
            #pragma unroll
            for (int ks = 0; ks < 8; ks++) {
                unsigned b0[8], b1[8];
                int brow = ks * 8 + (lane & 3);
                #pragma unroll
                for (int nt = 0; nt < 8; nt++) {
                    int bcol = wn * 64 + nt * 8 + (lane >> 2);
                    b0[nt] = Bs[brow * LDBg + bcol];
                    b1[nt] = Bs[(brow + 4) * LDBg + bcol];
                }
                unsigned a[2][4];
                int acol = ks * 8 + (lane & 3);
                #pragma unroll
                for (int mt = 0; mt < 2; mt++) {
                    int r = wm * 32 + mt * 16 + (lane >> 2);
                    a[mt][0] = As[r * LDAg + acol];
                    a[mt][1] = As[(r + 8) * LDAg + acol];
                    a[mt][2] = As[r * LDAg + acol + 4];
                    a[mt][3] = As[(r + 8) * LDAg + acol + 4];
                }
                #pragma unroll
                for (int mt = 0; mt < 2; mt++)
                    #pragma unroll
                    for (int nt = 0; nt < 8; nt++) {
                        asm volatile(
                            "mma.sync.aligned.m16n8k8.row.col.f32.tf32.tf32.f32 "
                            "{%0,%1,%2,%3}, {%4,%5,%6,%7}, {%8,%9}, {%0,%1,%2,%3};\n"
                            : "+f"(acc[mt][nt][0]), "+f"(acc[mt][nt][1]),
                              "+f"(acc[mt][nt][2]), "+f"(acc[mt][nt][3])
                            : "r"(a[mt][0]), "r"(a[mt][1]), "r"(a[mt][2]), "r"(a[mt][3]),
                              "r"(b0[nt]), "r"(b1[nt]));
                    }
            }
        }
        __syncthreads();
    }

    #pragma unroll
    for (int mt = 0; mt < 2; mt++) {
        #pragma unroll
        for (int nt = 0; nt < 8; nt++) {
            int row = m0 + wm * 32 + mt * 16 + (lane >> 2);
            int col = wn * 64 + nt * 8 + (lane & 3) * 2;
            int fidx = z * 2 + (col >> 7);
            int c    = col & 127;
            float* __restrict__ O = g_O + (long long)fidx * SLAB;
            float bv0 = bias[fidx * 128 + c];
            float bv1 = bias[fidx * 128 + c + 1];
            if (row < n) {
                float2 r01 = make_float2(acc[mt][nt][0] + bv0, acc[mt][nt][1] + bv1);
                *(float2*)&O[(long long)row * 128 + c] = r01;
            }
            if (row + 8 < n) {
                float2 r23 = make_float2(acc[mt][nt][2] + bv0, acc[mt][nt][3] + bv1);
                *(float2*)&O[(long long)(row + 8) * 128 + c] = r23;
            }
        }
    }
}

// --------------------------------------- attention + softmax + layernorm ----

__device__ __forceinline__ void fma4s(float4& a, float s, const float4 w) {
    a.x = fmaf(s, w.x, a.x); a.y = fmaf(s, w.y, a.y);
    a.z = fmaf(s, w.z, a.z); a.w = fmaf(s, w.w, a.w);
}

__global__ void __launch_bounds__(256)
final_kernel(const float* __restrict__ attn_w, const float* __restrict__ attn_b,
             const float* __restrict__ ln_g, const float* __restrict__ ln_b,
             float* __restrict__ out, int n) {
    int gw = (blockIdx.x * blockDim.x + threadIdx.x) >> 5;
    if (gw >= n) return;
    int lane = threadIdx.x & 31;

    float4 v[NFILT];
    #pragma unroll
    for (int f = 0; f < NFILT; f++)
        v[f] = ((const float4*)(g_O + (long long)f * SLAB))[gw * 32 + lane];

    const float4* aw = (const float4*)attn_w;
    float4 lg = make_float4(0.f, 0.f, 0.f, 0.f);
    #pragma unroll
    for (int f = 0; f < NFILT; f++) {
        int base = f * 128 + lane * 4;
        fma4s(lg, v[f].x, aw[base + 0]);
        fma4s(lg, v[f].y, aw[base + 1]);
        fma4s(lg, v[f].z, aw[base + 2]);
        fma4s(lg, v[f].w, aw[base + 3]);
    }
    #pragma unroll
    for (int o = 16; o > 0; o >>= 1) {
        lg.x += __shfl_xor_sync(0xffffffffu, lg.x, o);
        lg.y += __shfl_xor_sync(0xffffffffu, lg.y, o);
        lg.z += __shfl_xor_sync(0xffffffffu, lg.z, o);
        lg.w += __shfl_xor_sync(0xffffffffu, lg.w, o);
    }
    lg.x += attn_b[0]; lg.y += attn_b[1]; lg.z += attn_b[2]; lg.w += attn_b[3];

    float mx = fmaxf(fmaxf(lg.x, lg.y), fmaxf(lg.z, lg.w));
    float e0 = expf(lg.x - mx), e1 = expf(lg.y - mx);
    float e2 = expf(lg.z - mx), e3 = expf(lg.w - mx);
    float inv_s = 1.0f / (e0 + e1 + e2 + e3);
    float a0 = e0 * inv_s, a1 = e1 * inv_s, a2 = e2 * inv_s, a3 = e3 * inv_s;

    float4 c = make_float4(0.f, 0.f, 0.f, 0.f);
    fma4s(c, a0, v[0]); fma4s(c, a1, v[1]);
    fma4s(c, a2, v[2]); fma4s(c, a3, v[3]);

    float s = c.x + c.y + c.z + c.w;
    #pragma unroll
    for (int o = 16; o > 0; o >>= 1) s += __shfl_xor_sync(0xffffffffu, s, o);
    float mu = s * (1.0f / 128.0f);

    float dx = c.x - mu, dy = c.y - mu, dz = c.z - mu, dw = c.w - mu;
    float sq = dx * dx + dy * dy + dz * dz + dw * dw;
    #pragma unroll
    for (int o = 16; o > 0; o >>= 1) sq += __shfl_xor_sync(0xffffffffu, sq, o);
    float var = sq * (1.0f / 128.0f);
    float inv = rsqrtf(var + 1e-5f);

    float4 g = ((const float4*)ln_g)[lane];
    float4 b = ((const float4*)ln_b)[lane];
    float4 r = make_float4(dx * inv * g.x + b.x, dy * inv * g.y + b.y,
                           dz * inv * g.z + b.z, dw * inv * g.w + b.w);
    ((float4*)out)[gw * 32 + lane] = r;
}

// -------------------------------------------------------------- launch ----

extern "C" void kernel_launch(void* const* d_in, const int* in_sizes, int n_in,
                              void* d_out, int out_size) {
    const float* x      = (const float*)d_in[0];
    const void*  ei     = d_in[1];
    const float* cheb_w = (const float*)d_in[2];
    const float* cheb_b = (const float*)d_in[3];
    const float* attn_w = (const float*)d_in[4];
    const float* attn_b = (const float*)d_in[5];
    const float* ln_g   = (const float*)d_in[6];
    const float* ln_b   = (const float*)d_in[7];
    float* out = (float*)d_out;

    int n = in_sizes[0] / C_IN;
    int E = in_sizes[1] / 2;
    int n4 = n * 32;

    // launch order: ncu captures launch index 3 -> prop step k=2
    init_kernel<<<2048, 256>>>((const float4*)x, n4, n, (const int*)ei, 2 * E); // 0
    build_kernel<<<NBLK, 256>>>(ei, E, n);                                      // 1

    int pb = (n + 7) / 8;
    prop_kernel<<<pb, 256>>>(1, 0, 0, 1, n);                                    // 2
    for (int k = 2; k < MAXK; k++)                                              // 3 = k2 (profiled)
        prop_kernel<<<pb, 256>>>(k, k - 1, k - 2, 0, n);

    cudaFuncSetAttribute(gemm_kernel,
                         cudaFuncAttributeMaxDynamicSharedMemorySize, GEMM_SMEM);
    dim3 ggrid((n + 127) / 128, 1, 2);
    gemm_kernel<<<ggrid, 512, GEMM_SMEM>>>(cheb_w, cheb_b, n);

    final_kernel<<<pb, 256>>>(attn_w, attn_b, ln_g, ln_b, out, n);
}

// round 11
// speedup vs baseline: 1.0814x; 1.0814x over previous
#include <cuda_runtime.h>
#include <math.h>

#define C_IN   128
#define NMAX   50000
#define EMAX   800000
#define SLAB   (NMAX * C_IN)
#define MAXK   20
#define NFILT  4
#define NBLK   148

__device__ float g_Y[(long long)MAXK * SLAB];   // Tx_0..Tx_19
__device__ float g_O[(long long)NFILT * SLAB];  // filter outputs
__device__ int2  g_csr[EMAX];                   // {src, float_bits(w)} grouped by dst
__device__ int   g_rowptr[NMAX + 1];
__device__ int   g_deg[NMAX];
__device__ int   g_indeg[NMAX];
__device__ int   g_fill[NMAX];
__device__ float g_dinv[NMAX];
__device__ int   g_is64;
__device__ unsigned g_bar;
__device__ int   g_bsum[NBLK];

// ----------------------------------------------------------- fused init ----

__global__ void init_kernel(const float4* __restrict__ x, int n4, int n,
                            const int* __restrict__ ei32, int E2) {
    int stride = gridDim.x * blockDim.x;
    int g = blockIdx.x * blockDim.x + threadIdx.x;
    float4* dst = (float4*)g_Y;
    for (int i = g; i < n4; i += stride) dst[i] = x[i];
    for (int i = g; i < n; i += stride) { g_deg[i] = 0; g_indeg[i] = 0; g_fill[i] = 0; }
    if (g == 0) g_bar = 0;
    if (blockIdx.x == 0) {
        __shared__ int any_nonzero;
        if (threadIdx.x == 0) any_nonzero = 0;
        __syncthreads();
        for (int i = threadIdx.x; i < 4096; i += blockDim.x) {
            int idx = 2 * i + 1;
            if (idx < E2 && ei32[idx] != 0) any_nonzero = 1;
        }
        __syncthreads();
        if (threadIdx.x == 0) g_is64 = any_nonzero ? 0 : 1;
    }
}

__device__ __forceinline__ int load_idx(const void* ei, long long pos) {
    if (g_is64) return (int)((const long long*)ei)[pos];
    return ((const int*)ei)[pos];
}

// -------------------------------------------------- fused graph build ------

__device__ __forceinline__ void grid_sync(int phase) {
    __syncthreads();
    if (threadIdx.x == 0) {
        __threadfence();
        atomicAdd(&g_bar, 1u);
        unsigned target = (unsigned)phase * (unsigned)gridDim.x;
        while (atomicAdd(&g_bar, 0u) < target) { }
    }
    __syncthreads();
}

__global__ void __launch_bounds__(256) build_kernel(const void* __restrict__ ei,
                                                    int E, int n) {
    const int tid = threadIdx.x, bid = blockIdx.x, nb = gridDim.x;
    const int lane = tid & 31, wid = tid >> 5;
    const int gsz = nb * 256;
    const int g = bid * 256 + tid;

    for (int e = g; e < E; e += gsz) {
        int s = load_idx(ei, e);
        int d = load_idx(ei, (long long)E + e);
        if ((unsigned)s < (unsigned)n) atomicAdd(&g_deg[s], 1);
        if ((unsigned)d < (unsigned)n) atomicAdd(&g_indeg[d], 1);
    }
    grid_sync(1);

    for (int i = g; i < n; i += gsz) {
        int d = g_deg[i];
        g_dinv[i] = (d > 0) ? rsqrtf((float)d) : 0.0f;
    }
    const int chunk = (n + nb - 1) / nb;
    const int c0 = bid * chunk;
    const int c1 = min(c0 + chunk, n);
    int local = 0;
    for (int i = c0 + tid; i < c1; i += 256) local += g_indeg[i];
    __shared__ int red[32];
    #pragma unroll
    for (int o = 16; o > 0; o >>= 1) local += __shfl_xor_sync(0xffffffffu, local, o);
    if (lane == 0) red[wid] = local;
    __syncthreads();
    if (wid == 0) {
        int v = (lane < 8) ? red[lane] : 0;
        #pragma unroll
        for (int o = 4; o > 0; o >>= 1) v += __shfl_xor_sync(0xffffffffu, v, o);
        if (lane == 0) g_bsum[bid] = v;
    }
    grid_sync(2);

    if (bid == 0 && wid == 0) {
        int run = 0;
        for (int s0 = 0; s0 < nb; s0 += 32) {
            int i = s0 + lane;
            int v = (i < nb) ? g_bsum[i] : 0;
            int x = v;
            #pragma unroll
            for (int d = 1; d < 32; d <<= 1) {
                int y = __shfl_up_sync(0xffffffffu, x, d);
                if (lane >= d) x += y;
            }
            if (i < nb) g_bsum[i] = run + x - v;
            run += __shfl_sync(0xffffffffu, x, 31);
        }
    }
    grid_sync(3);

    {
        int carry = g_bsum[bid];
        if (bid == 0 && tid == 0) g_rowptr[0] = 0;
        __shared__ int wsum[8];
        for (int s0 = c0; s0 < c1; s0 += 256) {
            int i = s0 + tid;
            int v = (i < c1) ? g_indeg[i] : 0;
            int x = v;
            #pragma unroll
            for (int d = 1; d < 32; d <<= 1) {
                int y = __shfl_up_sync(0xffffffffu, x, d);
                if (lane >= d) x += y;
            }
            if (lane == 31) wsum[wid] = x;
            __syncthreads();
            if (wid == 0 && lane < 8) {
                int s = wsum[lane];
                #pragma unroll
                for (int d = 1; d < 8; d <<= 1) {
                    int y = __shfl_up_sync(0xffu, s, d);
                    if (lane >= d) s += y;
                }
                wsum[lane] = s;
            }
            __syncthreads();
            int pre = (wid > 0) ? wsum[wid - 1] : 0;
            if (i < c1) g_rowptr[i + 1] = carry + pre + x;
            carry += wsum[7];
            __syncthreads();
        }
    }
    grid_sync(4);

    for (int e = g; e < E; e += gsz) {
        int s = load_idx(ei, e);
        int d = load_idx(ei, (long long)E + e);
        if ((unsigned)s >= (unsigned)n || (unsigned)d >= (unsigned)n) continue;
        float w = -g_dinv[s] * g_dinv[d] - 1.0f;   // self-loops -> exactly 0, omitted
        int pos = g_rowptr[d] + atomicAdd(&g_fill[d], 1);
        if (pos < EMAX) g_csr[pos] = make_int2(s, __float_as_int(w));
    }
}

// ---------------------------------------------------------- propagation ----
// R9 optimum: warp-per-node, MLP=2, csr prefetched one iteration ahead.
// (Deeper pipelining raises regs and kills occupancy — measured regression.)

__device__ __forceinline__ void fma4(float4& a, float w, const float4 v) {
    a.x = fmaf(w, v.x, a.x); a.y = fmaf(w, v.y, a.y);
    a.z = fmaf(w, v.z, a.z); a.w = fmaf(w, v.w, a.w);
}

__global__ void __launch_bounds__(256, 6) prop_kernel(int outSlab, int inSlab,
                                                      int prevSlab, int first, int n) {
    int gw = (blockIdx.x * blockDim.x + threadIdx.x) >> 5;
    if (gw >= n) return;
    int lane = threadIdx.x & 31;
    const float4* __restrict__ Yin = (const float4*)(g_Y + (long long)inSlab * SLAB);
    int s = g_rowptr[gw], e = g_rowptr[gw + 1];
    float4 a0 = make_float4(0.f, 0.f, 0.f, 0.f);
    float4 a1 = make_float4(0.f, 0.f, 0.f, 0.f);
    int i = s;
    int2 p0, p1;
    if (i < e)     p0 = g_csr[i];
    if (i + 1 < e) p1 = g_csr[i + 1];
    for (; i + 2 <= e; i += 2) {
        int2 q0 = g_csr[min(i + 2, EMAX - 1)];   // prefetch next iter (clamped)
        int2 q1 = g_csr[min(i + 3, EMAX - 1)];
        float4 v0 = Yin[p0.x * 32 + lane];
        float4 v1 = Yin[p1.x * 32 + lane];
        fma4(a0, __int_as_float(p0.y), v0);
        fma4(a1, __int_as_float(p1.y), v1);
        p0 = q0; p1 = q1;
    }
    if (i < e) {   // exactly one edge left; p0 == csr[i]
        float4 v = Yin[p0.x * 32 + lane];
        fma4(a0, __int_as_float(p0.y), v);
    }
    float4 r = make_float4(a0.x + a1.x, a0.y + a1.y, a0.z + a1.z, a0.w + a1.w);
    if (!first) {
        const float4* Yp = (const float4*)(g_Y + (long long)prevSlab * SLAB);
        float4 pv = Yp[gw * 32 + lane];
        r.x = 2.f * r.x - pv.x; r.y = 2.f * r.y - pv.y;
        r.z = 2.f * r.z - pv.z; r.w = 2.f * r.w - pv.w;
    }
    ((float4*)(g_Y + (long long)outSlab * SLAB))[gw * 32 + lane] = r;
}

// ------------------------------------------------------------ tf32 GEMM ----
// Fused filter pairs (z=0: f0,f1 | z=1: f2,f3), CTA 128(M)x256(N).
// 3-stage cp.async pipeline, kc=32 chunks, ONE __syncthreads per chunk:
// body = { wait_group 1; sync; mma(c); load(c+2); commit; }.
// With 3 stages, load target (c+2)%3 == (c-1)%3 was last read in mma(c-1),
// which every warp completed before this chunk's barrier -> no post-mma sync.

#define KCg 32
#define LDAg 36
#define LDBg 264
#define A_STAGE (128 * LDAg)
#define B_STAGE (KCg * LDBg)
#define NSTAGE 3
#define GEMM_SMEM ((NSTAGE * (A_STAGE + B_STAGE)) * 4)

__device__ __forceinline__ void cp16(unsigned dst, const void* src, int srcsz) {
    asm volatile("cp.async.cg.shared.global [%0], [%1], 16, %2;\n"
                 :: "r"(dst), "l"(src), "r"(srcsz));
}

__global__ void __launch_bounds__(512, 1)
gemm_kernel(const float* __restrict__ Wg, const float* __restrict__ bias, int n) {
    extern __shared__ unsigned smem_u[];

    const int z = blockIdx.z;
    const int KfA  = z ? 15 : 5;
    const int KfB  = z ? 20 : 10;
    const int offA = z ? 15 : 0;
    const int offB = z ? 30 : 5;
    const int nChunk = KfB * 4;            // kc=32, K=128 per slab

    const int m0  = blockIdx.x * 128;
    const int tid = threadIdx.x;
    const int warp = tid >> 5, lane = tid & 31;
    const int wm = warp & 3, wn = warp >> 2;
    const int myK = (wn < 2) ? KfA : KfB;

    const unsigned smemBase = (unsigned)__cvta_generic_to_shared(smem_u);
    const unsigned bsBase   = smemBase + (unsigned)(NSTAGE * A_STAGE) * 4u;

    float acc[2][8][4];
    #pragma unroll
    for (int a = 0; a < 2; a++)
        #pragma unroll
        for (int b = 0; b < 8; b++)
            #pragma unroll
            for (int c = 0; c < 4; c++) acc[a][b][c] = 0.f;

    auto load_chunk = [&](int c) {
        int st   = c % NSTAGE;
        int slab = c >> 2;
        int kc0  = (c & 3) * KCg;
        const float* A = g_Y + (long long)slab * SLAB;
        unsigned as = smemBase + (unsigned)(st * A_STAGE) * 4u;
        #pragma unroll
        for (int j = 0; j < 2; j++) {          // A: 128 x 32 floats = 1024 cp16
            int i = tid + j * 512;
            int r = i >> 3, c16 = i & 7;
            int row = m0 + r;
            const float* src = A + (long long)row * 128 + kc0 + c16 * 4;
            cp16(as + (unsigned)(r * LDAg + c16 * 4) * 4u, src, (row < n) ? 16 : 0);
        }
        unsigned bs = bsBase + (unsigned)(st * B_STAGE) * 4u;
        #pragma unroll
        for (int j = 0; j < 4; j++) {          // B: 32 x 256 floats = 2048 cp16
            int i = tid + j * 512;
            int half = i >> 10, ii = i & 1023;
            int r = ii >> 5, c16 = ii & 31;
            int Kh   = half ? KfB : KfA;
            int offh = half ? offB : offA;
            if (slab < Kh) {
                const float* src = Wg + (long long)(offh + slab) * 16384
                                      + (kc0 + r) * 128 + c16 * 4;
                cp16(bs + (unsigned)(r * LDBg + half * 128 + c16 * 4) * 4u, src, 16);
            }
        }
        asm volatile("cp.async.commit_group;\n");
    };

    load_chunk(0);
    load_chunk(1);
    for (int c = 0; c < nChunk; c++) {
        asm volatile("cp.async.wait_group 1;\n");
        __syncthreads();

        int slab = c >> 2;
        if (slab < myK) {
            int st = c % NSTAGE;
            const unsigned* As = smem_u + st * A_STAGE;
            const unsigned* Bs = smem_u + NSTAGE * A_STAGE + st * B_STAGE;
            #pragma unroll
            for (int ks = 0; ks < 4; ks++) {
                unsigned b0[8], b1[8];
                int brow = ks * 8 + (lane & 3);
                #pragma unroll
                for (int nt = 0; nt < 8; nt++) {
                    int bcol = wn * 64 + nt * 8 + (lane >> 2);
                    b0[nt] = Bs[brow * LDBg + bcol];
                    b1[nt] = Bs[(brow + 4) * LDBg + bcol];
                }
                unsigned a[2][4];
                int acol = ks * 8 + (lane & 3);
                #pragma unroll
                for (int mt = 0; mt < 2; mt++) {
                    int r = wm * 32 + mt * 16 + (lane >> 2);
                    a[mt][0] = As[r * LDAg + acol];
                    a[mt][1] = As[(r + 8) * LDAg + acol];
                    a[mt][2] = As[r * LDAg + acol + 4];
                    a[mt][3] = As[(r + 8) * LDAg + acol + 4];
                }
                #pragma unroll
                for (int mt = 0; mt < 2; mt++)
                    #pragma unroll
                    for (int nt = 0; nt < 8; nt++) {
                        asm volatile(
                            "mma.sync.aligned.m16n8k8.row.col.f32.tf32.tf32.f32 "
                            "{%0,%1,%2,%3}, {%4,%5,%6,%7}, {%8,%9}, {%0,%1,%2,%3};\n"
                            : "+f"(acc[mt][nt][0]), "+f"(acc[mt][nt][1]),
                              "+f"(acc[mt][nt][2]), "+f"(acc[mt][nt][3])
                            : "r"(a[mt][0]), "r"(a[mt][1]), "r"(a[mt][2]), "r"(a[mt][3]),
                              "r"(b0[nt]), "r"(b1[nt]));
                    }
            }
        }

        if (c + 2 < nChunk) load_chunk(c + 2);
        else asm volatile("cp.async.commit_group;\n");
    }

    #pragma unroll
    for (int mt = 0; mt < 2; mt++) {
        #pragma unroll
        for (int nt = 0; nt < 8; nt++) {
            int row = m0 + wm * 32 + mt * 16 + (lane >> 2);
            int col = wn * 64 + nt * 8 + (lane & 3) * 2;
            int fidx = z * 2 + (col >> 7);
            int c    = col & 127;
            float* __restrict__ O = g_O + (long long)fidx * SLAB;
            float bv0 = bias[fidx * 128 + c];
            float bv1 = bias[fidx * 128 + c + 1];
            if (row < n) {
                float2 r01 = make_float2(acc[mt][nt][0] + bv0, acc[mt][nt][1] + bv1);
                *(float2*)&O[(long long)row * 128 + c] = r01;
            }
            if (row + 8 < n) {
                float2 r23 = make_float2(acc[mt][nt][2] + bv0, acc[mt][nt][3] + bv1);
                *(float2*)&O[(long long)(row + 8) * 128 + c] = r23;
            }
        }
    }
}

// --------------------------------------- attention + softmax + layernorm ----

__device__ __forceinline__ void fma4s(float4& a, float s, const float4 w) {
    a.x = fmaf(s, w.x, a.x); a.y = fmaf(s, w.y, a.y);
    a.z = fmaf(s, w.z, a.z); a.w = fmaf(s, w.w, a.w);
}

__global__ void __launch_bounds__(256)
final_kernel(const float* __restrict__ attn_w, const float* __restrict__ attn_b,
             const float* __restrict__ ln_g, const float* __restrict__ ln_b,
             float* __restrict__ out, int n) {
    int gw = (blockIdx.x * blockDim.x + threadIdx.x) >> 5;
    if (gw >= n) return;
    int lane = threadIdx.x & 31;

    float4 v[NFILT];
    #pragma unroll
    for (int f = 0; f < NFILT; f++)
        v[f] = ((const float4*)(g_O + (long long)f * SLAB))[gw * 32 + lane];

    const float4* aw = (const float4*)attn_w;
    float4 lg = make_float4(0.f, 0.f, 0.f, 0.f);
    #pragma unroll
    for (int f = 0; f < NFILT; f++) {
        int base = f * 128 + lane * 4;
        fma4s(lg, v[f].x, aw[base + 0]);
        fma4s(lg, v[f].y, aw[base + 1]);
        fma4s(lg, v[f].z, aw[base + 2]);
        fma4s(lg, v[f].w, aw[base + 3]);
    }
    #pragma unroll
    for (int o = 16; o > 0; o >>= 1) {
        lg.x += __shfl_xor_sync(0xffffffffu, lg.x, o);
        lg.y += __shfl_xor_sync(0xffffffffu, lg.y, o);
        lg.z += __shfl_xor_sync(0xffffffffu, lg.z, o);
        lg.w += __shfl_xor_sync(0xffffffffu, lg.w, o);
    }
    lg.x += attn_b[0]; lg.y += attn_b[1]; lg.z += attn_b[2]; lg.w += attn_b[3];

    float mx = fmaxf(fmaxf(lg.x, lg.y), fmaxf(lg.z, lg.w));
    float e0 = expf(lg.x - mx), e1 = expf(lg.y - mx);
    float e2 = expf(lg.z - mx), e3 = expf(lg.w - mx);
    float inv_s = 1.0f / (e0 + e1 + e2 + e3);
    float a0 = e0 * inv_s, a1 = e1 * inv_s, a2 = e2 * inv_s, a3 = e3 * inv_s;

    float4 c = make_float4(0.f, 0.f, 0.f, 0.f);
    fma4s(c, a0, v[0]); fma4s(c, a1, v[1]);
    fma4s(c, a2, v[2]); fma4s(c, a3, v[3]);

    float s = c.x + c.y + c.z + c.w;
    #pragma unroll
    for (int o = 16; o > 0; o >>= 1) s += __shfl_xor_sync(0xffffffffu, s, o);
    float mu = s * (1.0f / 128.0f);

    float dx = c.x - mu, dy = c.y - mu, dz = c.z - mu, dw = c.w - mu;
    float sq = dx * dx + dy * dy + dz * dz + dw * dw;
    #pragma unroll
    for (int o = 16; o > 0; o >>= 1) sq += __shfl_xor_sync(0xffffffffu, sq, o);
    float var = sq * (1.0f / 128.0f);
    float inv = rsqrtf(var + 1e-5f);

    float4 g = ((const float4*)ln_g)[lane];
    float4 b = ((const float4*)ln_b)[lane];
    float4 r = make_float4(dx * inv * g.x + b.x, dy * inv * g.y + b.y,
                           dz * inv * g.z + b.z, dw * inv * g.w + b.w);
    ((float4*)out)[gw * 32 + lane] = r;
}

// -------------------------------------------------------------- launch ----

extern "C" void kernel_launch(void* const* d_in, const int* in_sizes, int n_in,
                              void* d_out, int out_size) {
    const float* x      = (const float*)d_in[0];
    const void*  ei     = d_in[1];
    const float* cheb_w = (const float*)d_in[2];
    const float* cheb_b = (const float*)d_in[3];
    const float* attn_w = (const float*)d_in[4];
    const float* attn_b = (const float*)d_in[5];
    const float* ln_g   = (const float*)d_in[6];
    const float* ln_b   = (const float*)d_in[7];
    float* out = (float*)d_out;

    int n = in_sizes[0] / C_IN;
    int E = in_sizes[1] / 2;
    int n4 = n * 32;

    // launch order: ncu captures launch index 3 -> prop step k=2
    init_kernel<<<2048, 256>>>((const float4*)x, n4, n, (const int*)ei, 2 * E); // 0
    build_kernel<<<NBLK, 256>>>(ei, E, n);                                      // 1

    int pb = (n + 7) / 8;
    prop_kernel<<<pb, 256>>>(1, 0, 0, 1, n);                                    // 2
    for (int k = 2; k < MAXK; k++)                                              // 3 = k2 (profiled)
        prop_kernel<<<pb, 256>>>(k, k - 1, k - 2, 0, n);

    cudaFuncSetAttribute(gemm_kernel,
                         cudaFuncAttributeMaxDynamicSharedMemorySize, GEMM_SMEM);
    dim3 ggrid((n + 127) / 128, 1, 2);
    gemm_kernel<<<ggrid, 512, GEMM_SMEM>>>(cheb_w, cheb_b, n);

    final_kernel<<<pb, 256>>>(attn_w, attn_b, ln_g, ln_b, out, n);
}

// round 12
// speedup vs baseline: 1.1144x; 1.0304x over previous
#include <cuda_runtime.h>
#include <math.h>

#define C_IN   128
#define NMAX   50000
#define EMAX   800000
#define SLAB   (NMAX * C_IN)
#define MAXK   20
#define NFILT  4
#define NBLK   148

__device__ float g_Y[(long long)MAXK * SLAB];   // Tx_0..Tx_19
__device__ float g_O[(long long)NFILT * SLAB];  // filter outputs
__device__ int2  g_csr[EMAX];                   // {src, float_bits(w)} grouped by dst
__device__ int   g_rowptr[NMAX + 1];
__device__ int   g_deg[NMAX];
__device__ int   g_indeg[NMAX];
__device__ int   g_fill[NMAX];
__device__ float g_dinv[NMAX];
__device__ int   g_is64;
__device__ unsigned g_bar;
__device__ int   g_bsum[NBLK];

// ----------------------------------------------------------- fused init ----

__global__ void init_kernel(const float4* __restrict__ x, int n4, int n,
                            const int* __restrict__ ei32, int E2) {
    int stride = gridDim.x * blockDim.x;
    int g = blockIdx.x * blockDim.x + threadIdx.x;
    float4* dst = (float4*)g_Y;
    for (int i = g; i < n4; i += stride) dst[i] = x[i];
    for (int i = g; i < n; i += stride) { g_deg[i] = 0; g_indeg[i] = 0; g_fill[i] = 0; }
    if (g == 0) g_bar = 0;
    if (blockIdx.x == 0) {
        __shared__ int any_nonzero;
        if (threadIdx.x == 0) any_nonzero = 0;
        __syncthreads();
        for (int i = threadIdx.x; i < 4096; i += blockDim.x) {
            int idx = 2 * i + 1;
            if (idx < E2 && ei32[idx] != 0) any_nonzero = 1;
        }
        __syncthreads();
        if (threadIdx.x == 0) g_is64 = any_nonzero ? 0 : 1;
    }
}

__device__ __forceinline__ int load_idx(const void* ei, long long pos) {
    if (g_is64) return (int)((const long long*)ei)[pos];
    return ((const int*)ei)[pos];
}

// -------------------------------------------------- fused graph build ------

__device__ __forceinline__ void grid_sync(int phase) {
    __syncthreads();
    if (threadIdx.x == 0) {
        __threadfence();
        atomicAdd(&g_bar, 1u);
        unsigned target = (unsigned)phase * (unsigned)gridDim.x;
        while (atomicAdd(&g_bar, 0u) < target) { }
    }
    __syncthreads();
}

__global__ void __launch_bounds__(256) build_kernel(const void* __restrict__ ei,
                                                    int E, int n) {
    const int tid = threadIdx.x, bid = blockIdx.x, nb = gridDim.x;
    const int lane = tid & 31, wid = tid >> 5;
    const int gsz = nb * 256;
    const int g = bid * 256 + tid;

    for (int e = g; e < E; e += gsz) {
        int s = load_idx(ei, e);
        int d = load_idx(ei, (long long)E + e);
        if ((unsigned)s < (unsigned)n) atomicAdd(&g_deg[s], 1);
        if ((unsigned)d < (unsigned)n) atomicAdd(&g_indeg[d], 1);
    }
    grid_sync(1);

    for (int i = g; i < n; i += gsz) {
        int d = g_deg[i];
        g_dinv[i] = (d > 0) ? rsqrtf((float)d) : 0.0f;
    }
    const int chunk = (n + nb - 1) / nb;
    const int c0 = bid * chunk;
    const int c1 = min(c0 + chunk, n);
    int local = 0;
    for (int i = c0 + tid; i < c1; i += 256) local += g_indeg[i];
    __shared__ int red[32];
    #pragma unroll
    for (int o = 16; o > 0; o >>= 1) local += __shfl_xor_sync(0xffffffffu, local, o);
    if (lane == 0) red[wid] = local;
    __syncthreads();
    if (wid == 0) {
        int v = (lane < 8) ? red[lane] : 0;
        #pragma unroll
        for (int o = 4; o > 0; o >>= 1) v += __shfl_xor_sync(0xffffffffu, v, o);
        if (lane == 0) g_bsum[bid] = v;
    }
    grid_sync(2);

    if (bid == 0 && wid == 0) {
        int run = 0;
        for (int s0 = 0; s0 < nb; s0 += 32) {
            int i = s0 + lane;
            int v = (i < nb) ? g_bsum[i] : 0;
            int x = v;
            #pragma unroll
            for (int d = 1; d < 32; d <<= 1) {
                int y = __shfl_up_sync(0xffffffffu, x, d);
                if (lane >= d) x += y;
            }
            if (i < nb) g_bsum[i] = run + x - v;
            run += __shfl_sync(0xffffffffu, x, 31);
        }
    }
    grid_sync(3);

    {
        int carry = g_bsum[bid];
        if (bid == 0 && tid == 0) g_rowptr[0] = 0;
        __shared__ int wsum[8];
        for (int s0 = c0; s0 < c1; s0 += 256) {
            int i = s0 + tid;
            int v = (i < c1) ? g_indeg[i] : 0;
            int x = v;
            #pragma unroll
            for (int d = 1; d < 32; d <<= 1) {
                int y = __shfl_up_sync(0xffffffffu, x, d);
                if (lane >= d) x += y;
            }
            if (lane == 31) wsum[wid] = x;
            __syncthreads();
            if (wid == 0 && lane < 8) {
                int s = wsum[lane];
                #pragma unroll
                for (int d = 1; d < 8; d <<= 1) {
                    int y = __shfl_up_sync(0xffu, s, d);
                    if (lane >= d) s += y;
                }
                wsum[lane] = s;
            }
            __syncthreads();
            int pre = (wid > 0) ? wsum[wid - 1] : 0;
            if (i < c1) g_rowptr[i + 1] = carry + pre + x;
            carry += wsum[7];
            __syncthreads();
        }
    }
    grid_sync(4);

    for (int e = g; e < E; e += gsz) {
        int s = load_idx(ei, e);
        int d = load_idx(ei, (long long)E + e);
        if ((unsigned)s >= (unsigned)n || (unsigned)d >= (unsigned)n) continue;
        float w = -g_dinv[s] * g_dinv[d] - 1.0f;   // self-loops -> exactly 0, omitted
        int pos = g_rowptr[d] + atomicAdd(&g_fill[d], 1);
        if (pos < EMAX) g_csr[pos] = make_int2(s, __float_as_int(w));
    }
}

// ---------------------------------------------------------- propagation ----
// R9/R11 optimum: warp-per-node, MLP=2, csr prefetched one iteration ahead.
// Measured AT the practical L2 roofline (~410 MB/step through LTS).

__device__ __forceinline__ void fma4(float4& a, float w, const float4 v) {
    a.x = fmaf(w, v.x, a.x); a.y = fmaf(w, v.y, a.y);
    a.z = fmaf(w, v.z, a.z); a.w = fmaf(w, v.w, a.w);
}

__global__ void __launch_bounds__(256, 6) prop_kernel(int outSlab, int inSlab,
                                                      int prevSlab, int first, int n) {
    int gw = (blockIdx.x * blockDim.x + threadIdx.x) >> 5;
    if (gw >= n) return;
    int lane = threadIdx.x & 31;
    const float4* __restrict__ Yin = (const float4*)(g_Y + (long long)inSlab * SLAB);
    int s = g_rowptr[gw], e = g_rowptr[gw + 1];
    float4 a0 = make_float4(0.f, 0.f, 0.f, 0.f);
    float4 a1 = make_float4(0.f, 0.f, 0.f, 0.f);
    int i = s;
    int2 p0, p1;
    if (i < e)     p0 = g_csr[i];
    if (i + 1 < e) p1 = g_csr[i + 1];
    for (; i + 2 <= e; i += 2) {
        int2 q0 = g_csr[min(i + 2, EMAX - 1)];   // prefetch next iter (clamped)
        int2 q1 = g_csr[min(i + 3, EMAX - 1)];
        float4 v0 = Yin[p0.x * 32 + lane];
        float4 v1 = Yin[p1.x * 32 + lane];
        fma4(a0, __int_as_float(p0.y), v0);
        fma4(a1, __int_as_float(p1.y), v1);
        p0 = q0; p1 = q1;
    }
    if (i < e) {   // exactly one edge left; p0 == csr[i]
        float4 v = Yin[p0.x * 32 + lane];
        fma4(a0, __int_as_float(p0.y), v);
    }
    float4 r = make_float4(a0.x + a1.x, a0.y + a1.y, a0.z + a1.z, a0.w + a1.w);
    if (!first) {
        const float4* Yp = (const float4*)(g_Y + (long long)prevSlab * SLAB);
        float4 pv = Yp[gw * 32 + lane];
        r.x = 2.f * r.x - pv.x; r.y = 2.f * r.y - pv.y;
        r.z = 2.f * r.z - pv.z; r.w = 2.f * r.w - pv.w;
    }
    ((float4*)(g_Y + (long long)outSlab * SLAB))[gw * 32 + lane] = r;
}

// ------------------------------------------------------------ tf32 GEMM ----
// Fused filter pairs, 3-stage cp.async pipeline, kc=32 chunks.
// Parameterized slab range [kLo,kHi) + accumulate flag so the GEMM can be
// split into a part overlapping the remaining prop steps (second stream).

#define KCg 32
#define LDAg 36
#define LDBg 264
#define A_STAGE (128 * LDAg)
#define B_STAGE (KCg * LDBg)
#define NSTAGE 3
#define GEMM_SMEM ((NSTAGE * (A_STAGE + B_STAGE)) * 4)

__device__ __forceinline__ void cp16(unsigned dst, const void* src, int srcsz) {
    asm volatile("cp.async.cg.shared.global [%0], [%1], 16, %2;\n"
                 :: "r"(dst), "l"(src), "r"(srcsz));
}

__global__ void __launch_bounds__(512, 1)
gemm_kernel(const float* __restrict__ Wg, const float* __restrict__ bias, int n,
            int zofs, int kLo, int kHi, int accum) {
    extern __shared__ unsigned smem_u[];

    const int z = blockIdx.z + zofs;
    const int KfA  = z ? 15 : 5;
    const int KfB  = z ? 20 : 10;
    const int offA = z ? 15 : 0;
    const int offB = z ? 30 : 5;
    const int kEnd = min(kHi, KfB);
    const int nChunk = (kEnd - kLo) * 4;   // kc=32, K=128 per slab

    const int m0  = blockIdx.x * 128;
    const int tid = threadIdx.x;
    const int warp = tid >> 5, lane = tid & 31;
    const int wm = warp & 3, wn = warp >> 2;
    const int myK = (wn < 2) ? KfA : KfB;

    const unsigned smemBase = (unsigned)__cvta_generic_to_shared(smem_u);
    const unsigned bsBase   = smemBase + (unsigned)(NSTAGE * A_STAGE) * 4u;

    float acc[2][8][4];
    #pragma unroll
    for (int a = 0; a < 2; a++)
        #pragma unroll
        for (int b = 0; b < 8; b++)
            #pragma unroll
            for (int c = 0; c < 4; c++) acc[a][b][c] = 0.f;

    auto load_chunk = [&](int c) {
        int st   = c % NSTAGE;
        int slab = kLo + (c >> 2);
        int kc0  = (c & 3) * KCg;
        const float* A = g_Y + (long long)slab * SLAB;
        unsigned as = smemBase + (unsigned)(st * A_STAGE) * 4u;
        #pragma unroll
        for (int j = 0; j < 2; j++) {          // A: 128 x 32 floats
            int i = tid + j * 512;
            int r = i >> 3, c16 = i & 7;
            int row = m0 + r;
            const float* src = A + (long long)row * 128 + kc0 + c16 * 4;
            cp16(as + (unsigned)(r * LDAg + c16 * 4) * 4u, src, (row < n) ? 16 : 0);
        }
        unsigned bs = bsBase + (unsigned)(st * B_STAGE) * 4u;
        #pragma unroll
        for (int j = 0; j < 4; j++) {          // B: 32 x 256 floats
            int i = tid + j * 512;
            int half = i >> 10, ii = i & 1023;
            int r = ii >> 5, c16 = ii & 31;
            int Kh   = half ? KfB : KfA;
            int offh = half ? offB : offA;
            if (slab < Kh) {
                const float* src = Wg + (long long)(offh + slab) * 16384
                                      + (kc0 + r) * 128 + c16 * 4;
                cp16(bs + (unsigned)(r * LDBg + half * 128 + c16 * 4) * 4u, src, 16);
            }
        }
        asm volatile("cp.async.commit_group;\n");
    };

    load_chunk(0);
    load_chunk(1);
    for (int c = 0; c < nChunk; c++) {
        asm volatile("cp.async.wait_group 1;\n");
        __syncthreads();

        int slab = kLo + (c >> 2);
        if (slab < myK) {
            int st = c % NSTAGE;
            const unsigned* As = smem_u + st * A_STAGE;
            const unsigned* Bs = smem_u + NSTAGE * A_STAGE + st * B_STAGE;
            #pragma unroll
            for (int ks = 0; ks < 4; ks++) {
                unsigned b0[8], b1[8];
                int brow = ks * 8 + (lane & 3);
                #pragma unroll
                for (int nt = 0; nt < 8; nt++) {
                    int bcol = wn * 64 + nt * 8 + (lane >> 2);
                    b0[nt] = Bs[brow * LDBg + bcol];
                    b1[nt] = Bs[(brow + 4) * LDBg + bcol];
                }
                unsigned a[2][4];
                int acol = ks * 8 + (lane & 3);
                #pragma unroll
                for (int mt = 0; mt < 2; mt++) {
                    int r = wm * 32 + mt * 16 + (lane >> 2);
                    a[mt][0] = As[r * LDAg + acol];
                    a[mt][1] = As[(r + 8) * LDAg + acol];
                    a[mt][2] = As[r * LDAg + acol + 4];
                    a[mt][3] = As[(r + 8) * LDAg + acol + 4];
                }
                #pragma unroll
                for (int mt = 0; mt < 2; mt++)
                    #pragma unroll
                    for (int nt = 0; nt < 8; nt++) {
                        asm volatile(
                            "mma.sync.aligned.m16n8k8.row.col.f32.tf32.tf32.f32 "
                            "{%0,%1,%2,%3}, {%4,%5,%6,%7}, {%8,%9}, {%0,%1,%2,%3};\n"
                            : "+f"(acc[mt][nt][0]), "+f"(acc[mt][nt][1]),
                              "+f"(acc[mt][nt][2]), "+f"(acc[mt][nt][3])
                            : "r"(a[mt][0]), "r"(a[mt][1]), "r"(a[mt][2]), "r"(a[mt][3]),
                              "r"(b0[nt]), "r"(b1[nt]));
                    }
            }
        }

        if (c + 2 < nChunk) load_chunk(c + 2);
        else asm volatile("cp.async.commit_group;\n");
    }

    #pragma unroll
    for (int mt = 0; mt < 2; mt++) {
        #pragma unroll
        for (int nt = 0; nt < 8; nt++) {
            int row = m0 + wm * 32 + mt * 16 + (lane >> 2);
            int col = wn * 64 + nt * 8 + (lane & 3) * 2;
            int fidx = z * 2 + (col >> 7);
            int c    = col & 127;
            float* __restrict__ O = g_O + (long long)fidx * SLAB;
            if (!accum) {
                float bv0 = bias[fidx * 128 + c];
                float bv1 = bias[fidx * 128 + c + 1];
                if (row < n) {
                    float2 r01 = make_float2(acc[mt][nt][0] + bv0, acc[mt][nt][1] + bv1);
                    *(float2*)&O[(long long)row * 128 + c] = r01;
                }
                if (row + 8 < n) {
                    float2 r23 = make_float2(acc[mt][nt][2] + bv0, acc[mt][nt][3] + bv1);
                    *(float2*)&O[(long long)(row + 8) * 128 + c] = r23;
                }
            } else {
                if (row < n) {
                    float2 o = *(float2*)&O[(long long)row * 128 + c];
                    o.x += acc[mt][nt][0]; o.y += acc[mt][nt][1];
                    *(float2*)&O[(long long)row * 128 + c] = o;
                }
                if (row + 8 < n) {
                    float2 o = *(float2*)&O[(long long)(row + 8) * 128 + c];
                    o.x += acc[mt][nt][2]; o.y += acc[mt][nt][3];
                    *(float2*)&O[(long long)(row + 8) * 128 + c] = o;
                }
            }
        }
    }
}

// --------------------------------------- attention + softmax + layernorm ----

__device__ __forceinline__ void fma4s(float4& a, float s, const float4 w) {
    a.x = fmaf(s, w.x, a.x); a.y = fmaf(s, w.y, a.y);
    a.z = fmaf(s, w.z, a.z); a.w = fmaf(s, w.w, a.w);
}

__global__ void __launch_bounds__(256)
final_kernel(const float* __restrict__ attn_w, const float* __restrict__ attn_b,
             const float* __restrict__ ln_g, const float* __restrict__ ln_b,
             float* __restrict__ out, int n) {
    int gw = (blockIdx.x * blockDim.x + threadIdx.x) >> 5;
    if (gw >= n) return;
    int lane = threadIdx.x & 31;

    float4 v[NFILT];
    #pragma unroll
    for (int f = 0; f < NFILT; f++)
        v[f] = ((const float4*)(g_O + (long long)f * SLAB))[gw * 32 + lane];

    const float4* aw = (const float4*)attn_w;
    float4 lg = make_float4(0.f, 0.f, 0.f, 0.f);
    #pragma unroll
    for (int f = 0; f < NFILT; f++) {
        int base = f * 128 + lane * 4;
        fma4s(lg, v[f].x, aw[base + 0]);
        fma4s(lg, v[f].y, aw[base + 1]);
        fma4s(lg, v[f].z, aw[base + 2]);
        fma4s(lg, v[f].w, aw[base + 3]);
    }
    #pragma unroll
    for (int o = 16; o > 0; o >>= 1) {
        lg.x += __shfl_xor_sync(0xffffffffu, lg.x, o);
        lg.y += __shfl_xor_sync(0xffffffffu, lg.y, o);
        lg.z += __shfl_xor_sync(0xffffffffu, lg.z, o);
        lg.w += __shfl_xor_sync(0xffffffffu, lg.w, o);
    }
    lg.x += attn_b[0]; lg.y += attn_b[1]; lg.z += attn_b[2]; lg.w += attn_b[3];

    float mx = fmaxf(fmaxf(lg.x, lg.y), fmaxf(lg.z, lg.w));
    float e0 = expf(lg.x - mx), e1 = expf(lg.y - mx);
    float e2 = expf(lg.z - mx), e3 = expf(lg.w - mx);
    float inv_s = 1.0f / (e0 + e1 + e2 + e3);
    float a0 = e0 * inv_s, a1 = e1 * inv_s, a2 = e2 * inv_s, a3 = e3 * inv_s;

    float4 c = make_float4(0.f, 0.f, 0.f, 0.f);
    fma4s(c, a0, v[0]); fma4s(c, a1, v[1]);
    fma4s(c, a2, v[2]); fma4s(c, a3, v[3]);

    float s = c.x + c.y + c.z + c.w;
    #pragma unroll
    for (int o = 16; o > 0; o >>= 1) s += __shfl_xor_sync(0xffffffffu, s, o);
    float mu = s * (1.0f / 128.0f);

    float dx = c.x - mu, dy = c.y - mu, dz = c.z - mu, dw = c.w - mu;
    float sq = dx * dx + dy * dy + dz * dz + dw * dw;
    #pragma unroll
    for (int o = 16; o > 0; o >>= 1) sq += __shfl_xor_sync(0xffffffffu, sq, o);
    float var = sq * (1.0f / 128.0f);
    float inv = rsqrtf(var + 1e-5f);

    float4 g = ((const float4*)ln_g)[lane];
    float4 b = ((const float4*)ln_b)[lane];
    float4 r = make_float4(dx * inv * g.x + b.x, dy * inv * g.y + b.y,
                           dz * inv * g.z + b.z, dw * inv * g.w + b.w);
    ((float4*)out)[gw * 32 + lane] = r;
}

// -------------------------------------------------------------- launch ----

extern "C" void kernel_launch(void* const* d_in, const int* in_sizes, int n_in,
                              void* d_out, int out_size) {
    const float* x      = (const float*)d_in[0];
    const void*  ei     = d_in[1];
    const float* cheb_w = (const float*)d_in[2];
    const float* cheb_b = (const float*)d_in[3];
    const float* attn_w = (const float*)d_in[4];
    const float* attn_b = (const float*)d_in[5];
    const float* ln_g   = (const float*)d_in[6];
    const float* ln_b   = (const float*)d_in[7];
    float* out = (float*)d_out;

    int n = in_sizes[0] / C_IN;
    int E = in_sizes[1] / 2;
    int n4 = n * 32;

    cudaFuncSetAttribute(gemm_kernel,
                         cudaFuncAttributeMaxDynamicSharedMemorySize, GEMM_SMEM);

    // fork stream + events (created per call; intentionally leaked — host-side
    // objects, kernel_launch runs only for correctness + capture)
    cudaStream_t s2;
    cudaStreamCreate(&s2);
    cudaEvent_t evFork, evJoinIn, evJoinOut;
    cudaEventCreateWithFlags(&evFork,    cudaEventDisableTiming);
    cudaEventCreateWithFlags(&evJoinIn,  cudaEventDisableTiming);
    cudaEventCreateWithFlags(&evJoinOut, cudaEventDisableTiming);

    // launch order: ncu captures launch index 3 -> prop step k=2
    init_kernel<<<2048, 256>>>((const float4*)x, n4, n, (const int*)ei, 2 * E); // 0
    build_kernel<<<NBLK, 256>>>(ei, E, n);                                      // 1

    int pb = (n + 7) / 8;
    prop_kernel<<<pb, 256>>>(1, 0, 0, 1, n);                                    // 2
    for (int k = 2; k <= 9; k++)                                                // 3..10
        prop_kernel<<<pb, 256>>>(k, k - 1, k - 2, 0, n);

    // fork: GEMM part1 (slabs 0-9, both pairs, writes O with bias) overlaps
    // props 10-19 on the main stream
    cudaEventRecord(evFork, 0);
    cudaStreamWaitEvent(s2, evFork, 0);
    dim3 g1((n + 127) / 128, 1, 2);
    gemm_kernel<<<g1, 512, GEMM_SMEM, s2>>>(cheb_w, cheb_b, n, 0, 0, 10, 0);

    for (int k = 10; k < MAXK; k++)
        prop_kernel<<<pb, 256>>>(k, k - 1, k - 2, 0, n);

    // join: part2 (pair f2/f3, slabs 10-19, accumulate) needs prop19 + part1
    cudaEventRecord(evJoinIn, 0);
    cudaStreamWaitEvent(s2, evJoinIn, 0);
    dim3 g2((n + 127) / 128, 1, 1);
    gemm_kernel<<<g2, 512, GEMM_SMEM, s2>>>(cheb_w, cheb_b, n, 1, 10, 20, 1);

    cudaEventRecord(evJoinOut, s2);
    cudaStreamWaitEvent(0, evJoinOut, 0);

    final_kernel<<<pb, 256>>>(attn_w, attn_b, ln_g, ln_b, out, n);
}